// round 15
// baseline (speedup 1.0000x reference)
#include <cuda_runtime.h>
#include <cuda_fp16.h>

// LightGCN: final = 0.25 * (I + A^ + A^2 + A^3) emb, A^ = D^-1/2 A D^-1/2
// N = 12000 (8000 users + 4000 items), dim 64, 300k undirected edges.
//
// R10: ELL stores pre-multiplied byte offsets (j<<7); rows pre-padded to 128
// slots with the zero-row offset (no selects in the hot loop); pointer-bumped
// index loads; +1 guard row so index prefetch never reads OOB. 128-thr blocks.

#define NUSERS 8000
#define NITEMS 4000
#define NN     12000
#define HALFN  6000
#define DIM    64
#define WPR    375            // bitmap words per row: ceil(12000/32)
#define PAD    128            // ELL row pad (mean deg ~50, P(>128) ~ 1e-20)
#define ZOFF   (NN * 128)     // byte offset of the permanent zero row

// Scratch (device globals: zero-init at load; left clean after every call).
__device__ unsigned g_bitmap[(size_t)NN * WPR];        // 18 MB dedup bitmap
__device__ int      g_nbr[(size_t)(NN + 1) * PAD];     // byte offsets (+guard row)
__device__ int      g_deg[NN];                         // build counter (reset each call)
__device__ int      g_deg2[NN];                        // snapshot for spmm
__device__ float    g_invd[NN];
__device__ __half   g_y[3][(size_t)(NN + 1) * DIM];    // +1: row NN is permanent zeros

// ---------------------------------------------------------------------------
// Dedup via bitmap atomicOr (old value elects exactly one winner per distinct
// directed edge); winner appends byte offset b<<7 to ELL. Self-loops once.
__device__ __forceinline__ void add_edge(int a, int b) {
    unsigned bit = 1u << (b & 31);
    unsigned old = atomicOr(&g_bitmap[(size_t)a * WPR + (b >> 5)], bit);
    if (!(old & bit)) {
        int pos = atomicAdd(&g_deg[a], 1);
        g_nbr[(size_t)a * PAD + pos] = b << 7;
    }
}

__global__ void build_kernel(const int* __restrict__ ei, int E) {
    int e = blockIdx.x * blockDim.x + threadIdx.x;
    if (e >= E) return;
    int u = ei[e];
    int v = ei[E + e];
    add_edge(u, v);
    add_edge(v, u);
}

// ---------------------------------------------------------------------------
// y0 = half(emb * d^-1/2); pad ELL slots [deg,128) with ZOFF; snapshot/reset
// deg; compute invd. 16 threads per row (one per float4).
__global__ void init_kernel(const float* __restrict__ ue,
                            const float* __restrict__ ie) {
    int i = blockIdx.x * blockDim.x + threadIdx.x;   // float4 index
    if (i >= NN * DIM / 4) return;
    int n = i >> 4;                                  // 16 float4 per row
    int t = i & 15;
    int d = g_deg[n];
    float id = rsqrtf((float)(d < 1 ? 1 : d));
    if (t == 0) {
        g_deg2[n] = d;
        g_deg[n]  = 0;                               // clean for next call
        g_invd[n] = id;
    }
    // Pad the ELL row (coalesced across the 16 threads of this row).
    for (int s = d + t; s < PAD; s += 16)
        g_nbr[(size_t)n * PAD + s] = ZOFF;

    float4 e = (n < NUSERS)
        ? reinterpret_cast<const float4*>(ue)[i]
        : reinterpret_cast<const float4*>(ie)[i - NUSERS * (DIM / 4)];
    __half2* yp = reinterpret_cast<__half2*>(g_y[0]) + (size_t)i * 2;
    yp[0] = __floats2half2_rn(e.x * id, e.y * id);
    yp[1] = __floats2half2_rn(e.z * id, e.w * id);
}

// ---------------------------------------------------------------------------
// Pair-sum two gathered 8-half chunks in fp16 (HADD2 x4), then convert & add
// into the fp32 accumulator.
__device__ __forceinline__ void acc8_pair(float acc[8], uint4 a, uint4 b) {
    __half2 h0 = __hadd2(*reinterpret_cast<__half2*>(&a.x),
                         *reinterpret_cast<__half2*>(&b.x));
    __half2 h1 = __hadd2(*reinterpret_cast<__half2*>(&a.y),
                         *reinterpret_cast<__half2*>(&b.y));
    __half2 h2 = __hadd2(*reinterpret_cast<__half2*>(&a.z),
                         *reinterpret_cast<__half2*>(&b.z));
    __half2 h3 = __hadd2(*reinterpret_cast<__half2*>(&a.w),
                         *reinterpret_cast<__half2*>(&b.w));
    float2 f0 = __half22float2(h0), f1 = __half22float2(h1);
    float2 f2 = __half22float2(h2), f3 = __half22float2(h3);
    acc[0] += f0.x; acc[1] += f0.y; acc[2] += f1.x; acc[3] += f1.y;
    acc[4] += f2.x; acc[5] += f2.y; acc[6] += f3.x; acc[7] += f3.y;
}

__device__ __forceinline__ void reduce_groups(float acc[8]) {
    #pragma unroll
    for (int i = 0; i < 8; ++i) {
        acc[i] += __shfl_xor_sync(0xffffffffu, acc[i], 8);
        acc[i] += __shfl_xor_sync(0xffffffffu, acc[i], 16);
    }
}

__device__ __forceinline__ void store_ynext(__half* dst, int row, int c,
                                            const float acc[8], float id) {
    float q = id * id;
    __half2 p0 = __floats2half2_rn(acc[0] * q, acc[1] * q);
    __half2 p1 = __floats2half2_rn(acc[2] * q, acc[3] * q);
    __half2 p2 = __floats2half2_rn(acc[4] * q, acc[5] * q);
    __half2 p3 = __floats2half2_rn(acc[6] * q, acc[7] * q);
    uint4 o;
    o.x = *reinterpret_cast<unsigned*>(&p0);
    o.y = *reinterpret_cast<unsigned*>(&p1);
    o.z = *reinterpret_cast<unsigned*>(&p2);
    o.w = *reinterpret_cast<unsigned*>(&p3);
    reinterpret_cast<uint4*>(dst)[(size_t)row * 8 + c] = o;
}

// out = 0.25 * (e + sqrt(d)*(y1+y2) + invd*s3). Full write, no RMW.
__device__ __forceinline__ void compose_out(float* __restrict__ out,
                                            const float* __restrict__ ue,
                                            const float* __restrict__ ie,
                                            int row, int c,
                                            const float acc[8],
                                            float id, float sd) {
    const float* e = (row < NUSERS) ? ue + (size_t)row * DIM
                                    : ie + (size_t)(row - NUSERS) * DIM;
    uint4 w1 = reinterpret_cast<const uint4*>(g_y[1])[(size_t)row * 8 + c];
    uint4 w2 = reinterpret_cast<const uint4*>(g_y[2])[(size_t)row * 8 + c];
    float4 e0 = reinterpret_cast<const float4*>(e + c * 8)[0];
    float4 e1 = reinterpret_cast<const float4*>(e + c * 8)[1];

    __half2 s0 = __hadd2(*reinterpret_cast<__half2*>(&w1.x),
                         *reinterpret_cast<__half2*>(&w2.x));
    __half2 s1 = __hadd2(*reinterpret_cast<__half2*>(&w1.y),
                         *reinterpret_cast<__half2*>(&w2.y));
    __half2 s2 = __hadd2(*reinterpret_cast<__half2*>(&w1.z),
                         *reinterpret_cast<__half2*>(&w2.z));
    __half2 s3h = __hadd2(*reinterpret_cast<__half2*>(&w1.w),
                          *reinterpret_cast<__half2*>(&w2.w));
    float2 y0 = __half22float2(s0), y1 = __half22float2(s1);
    float2 y2 = __half22float2(s2), y3 = __half22float2(s3h);

    float4 o0, o1;
    o0.x = 0.25f * (e0.x + sd * y0.x + id * acc[0]);
    o0.y = 0.25f * (e0.y + sd * y0.y + id * acc[1]);
    o0.z = 0.25f * (e0.z + sd * y1.x + id * acc[2]);
    o0.w = 0.25f * (e0.w + sd * y1.y + id * acc[3]);
    o1.x = 0.25f * (e1.x + sd * y2.x + id * acc[4]);
    o1.y = 0.25f * (e1.y + sd * y2.y + id * acc[5]);
    o1.z = 0.25f * (e1.z + sd * y3.x + id * acc[6]);
    o1.w = 0.25f * (e1.w + sd * y3.y + id * acc[7]);
    float4* op = reinterpret_cast<float4*>(out + (size_t)row * DIM + c * 8);
    op[0] = o0;
    op[1] = o1;
}

// One warp = rows (w, w+6000). Lane l: group g=l>>3 serves neighbor slots
// k+g / k+4+g; chunk c=l&7 owns dims [8c,8c+8). ELL rows are fully padded so
// the loop is branch-free: 4 imm-offset index loads (pipelined one iteration
// ahead) + 4 one-add-addressed LDG.128 gathers per iteration.
template <int SRC, int DST, bool LAST>
__global__ void __launch_bounds__(128, 8)
spmm_kernel(float* __restrict__ out,
            const float* __restrict__ ue, const float* __restrict__ ie) {
    const int w    = (blockIdx.x * 128 + threadIdx.x) >> 5;  // 0..5999
    const int lane = threadIdx.x & 31;
    const int g    = lane >> 3;
    const int c    = lane & 7;
    if (w >= HALFN) return;

    const int rA = w, rB = w + HALFN;
    const char* __restrict__ yb =
        reinterpret_cast<const char*>(g_y[SRC]) + c * 16;
    const int* pA = g_nbr + (size_t)rA * PAD + g;
    const int* pB = g_nbr + (size_t)rB * PAD + g;
    const int dA = g_deg2[rA];
    const int dB = g_deg2[rB];
    const int dmax = dA > dB ? dA : dB;

    float accA[8] = {0.f, 0.f, 0.f, 0.f, 0.f, 0.f, 0.f, 0.f};
    float accB[8] = {0.f, 0.f, 0.f, 0.f, 0.f, 0.f, 0.f, 0.f};

    // Pipelined byte offsets for the current iteration (padded slots -> ZOFF).
    int jA0 = __ldg(pA), jA1 = __ldg(pA + 4);
    int jB0 = __ldg(pB), jB1 = __ldg(pB + 4);

    for (int k = 0; k < dmax; k += 8) {
        pA += 8; pB += 8;
        int tA0 = __ldg(pA), tA1 = __ldg(pA + 4);   // guard row keeps in-bounds
        int tB0 = __ldg(pB), tB1 = __ldg(pB + 4);

        uint4 vA0 = *reinterpret_cast<const uint4*>(yb + jA0);
        uint4 vA1 = *reinterpret_cast<const uint4*>(yb + jA1);
        uint4 vB0 = *reinterpret_cast<const uint4*>(yb + jB0);
        uint4 vB1 = *reinterpret_cast<const uint4*>(yb + jB1);
        acc8_pair(accA, vA0, vA1);
        acc8_pair(accB, vB0, vB1);

        jA0 = tA0; jA1 = tA1; jB0 = tB0; jB1 = tB1;
    }

    reduce_groups(accA);
    reduce_groups(accB);

    const float idA = g_invd[rA];
    const float idB = g_invd[rB];

    if (!LAST) {
        if (g == 0) store_ynext(g_y[DST], rA, c, accA, idA);
        if (g == 2) store_ynext(g_y[DST], rB, c, accB, idB);
    } else {
        float sdA = sqrtf((float)(dA < 1 ? 1 : dA));
        float sdB = sqrtf((float)(dB < 1 ? 1 : dB));
        if (g == 1) compose_out(out, ue, ie, rA, c, accA, idA, sdA);
        if (g == 3) compose_out(out, ue, ie, rB, c, accB, idB, sdB);
        // Fold bitmap cleanup: offset>>12 == (j>>5), the touched word index.
        const int* nbA = g_nbr + (size_t)rA * PAD;
        const int* nbB = g_nbr + (size_t)rB * PAD;
        for (int k = lane; k < dA; k += 32)
            g_bitmap[(size_t)rA * WPR + (((unsigned)nbA[k]) >> 12)] = 0u;
        for (int k = lane; k < dB; k += 32)
            g_bitmap[(size_t)rB * WPR + (((unsigned)nbB[k]) >> 12)] = 0u;
    }
}

// ---------------------------------------------------------------------------
extern "C" void kernel_launch(void* const* d_in, const int* in_sizes, int n_in,
                              void* d_out, int out_size) {
    const int*   edge = (const int*)d_in[0];   // (2, E) int32
    const float* ue   = (const float*)d_in[1]; // (8000, 64) f32
    const float* ie   = (const float*)d_in[2]; // (4000, 64) f32
    float*       out  = (float*)d_out;         // (12000, 64) f32

    int E = in_sizes[0] / 2;

    build_kernel<<<(E + 255) / 256, 256>>>(edge, E);
    init_kernel<<<(NN * DIM / 4 + 255) / 256, 256>>>(ue, ie);

    const int SPMM_BLOCKS = (HALFN * 32) / 128;      // 1500 blocks, 4 warps each
    spmm_kernel<0, 1, false><<<SPMM_BLOCKS, 128>>>(out, ue, ie);
    spmm_kernel<1, 2, false><<<SPMM_BLOCKS, 128>>>(out, ue, ie);
    spmm_kernel<2, 0, true ><<<SPMM_BLOCKS, 128>>>(out, ue, ie);
}